// round 17
// baseline (speedup 1.0000x reference)
#include <cuda_runtime.h>
#include <cuda_fp16.h>
#include <cstdint>

#define FDIM    128
#define TP      128
#define NTHR    256
#define NGEMM   16
#define OMEGA_W 30.0f

// ---------------- smem layout (bytes) ----------------
#define SMEM_MB_W0   0
#define SMEM_MB_W1   8
#define SMEM_CS      64                    // 128*3 floats coords (1536 B)
#define SMEM_YBUF    2048                  // 4 x 128 fp32 (2 KB)
#define SMEM_XA      4096                  // X half A [128 f][64 n] fp16 (16 KB)
#define SMEM_XB      20480                 // X half B (16 KB)
#define SMEM_STGA    36864                 // d staging half A (32 KB fp32)
#define SMEM_STGB    69632                 // d staging half B (32 KB)
#define SMEM_WBUF0   102400                // weight buf 0 (32 KB)
#define SMEM_WBUF1   135168                // weight buf 1 (32 KB)
#define SMEM_TOTAL   167936

// Pre-converted, pre-swizzled fp16 weights: [gemm][128*128]
__device__ __align__(128) __half g_W[NGEMM][FDIM * FDIM];

// ---------------- PTX helpers ----------------
__device__ __forceinline__ uint32_t smem_u32(const void* p) {
    uint32_t a;
    asm("{ .reg .u64 t; cvta.to.shared.u64 t, %1; cvt.u32.u64 %0, t; }" : "=r"(a) : "l"(p));
    return a;
}
#define MBAR_INIT(mbar, cnt) \
    asm volatile("mbarrier.init.shared.b64 [%0], %1;" :: "r"(mbar), "r"(cnt) : "memory")
#define MBAR_EXPECT_TX(mbar, bytes) \
    asm volatile("mbarrier.arrive.expect_tx.shared.b64 _, [%0], %1;" :: "r"(mbar), "r"(bytes) : "memory")
#define MBAR_WAIT(mbar, ph) do {                                              \
    asm volatile("{\n\t.reg .pred P1;\n\t"                                    \
        "WL_%=:\n\t"                                                          \
        "mbarrier.try_wait.parity.acquire.cta.shared::cta.b64 P1, [%0], %1, 0x989680;\n\t" \
        "@P1 bra.uni WD_%=;\n\t"                                              \
        "bra.uni WL_%=;\n\t"                                                  \
        "WD_%=:\n\t}"                                                         \
        :: "r"(mbar), "r"(ph) : "memory");                                    \
} while (0)
#define BULK_G2S(dst, src, bytes, mbar) \
    asm volatile("cp.async.bulk.shared::cluster.global.mbarrier::complete_tx::bytes [%0], [%1], %2, [%3];" \
        :: "r"(dst), "l"(src), "r"(bytes), "r"(mbar) : "memory")

#define LDSM_X4(r, addr) \
    asm volatile("ldmatrix.sync.aligned.m8n8.x4.shared.b16 {%0,%1,%2,%3}, [%4];" \
        : "=r"((r)[0]), "=r"((r)[1]), "=r"((r)[2]), "=r"((r)[3]) : "r"(addr))
#define LDSM_X4T(r, addr) \
    asm volatile("ldmatrix.sync.aligned.m8n8.x4.trans.shared.b16 {%0,%1,%2,%3}, [%4];" \
        : "=r"((r)[0]), "=r"((r)[1]), "=r"((r)[2]), "=r"((r)[3]) : "r"(addr))

#define MMA16816(d, a, b0, b1) \
    asm volatile("mma.sync.aligned.m16n8k16.row.col.f32.f16.f16.f32 " \
        "{%0,%1,%2,%3},{%4,%5,%6,%7},{%8,%9},{%0,%1,%2,%3};" \
        : "+f"((d)[0]), "+f"((d)[1]), "+f"((d)[2]), "+f"((d)[3]) \
        : "r"((a)[0]), "r"((a)[1]), "r"((a)[2]), "r"((a)[3]), "r"(b0), "r"(b1))

// Weight tile: rows 256 B (128 fp16), XOR swizzle
__device__ __forceinline__ uint32_t woff(int f, int k) {
    return (uint32_t)(f * 256 + ((2 * k) ^ ((f & 7) << 4)));
}
// Activation half-tile: rows 128 B (64 fp16), XOR swizzle
__device__ __forceinline__ uint32_t xo64(int f, int n) {
    return (uint32_t)(f * 128 + ((2 * n) ^ ((f & 7) << 4)));
}
__device__ __forceinline__ void store_h16(char* xb, int f, int n, float v0, float v1) {
    *reinterpret_cast<__half2*>(xb + xo64(f, n)) = __floats2half2_rn(v0, v1);
}

// ---------------- weight prep: fp32 -> fp16, swizzled ----------------
__global__ void prep_weights_kernel(const float* __restrict__ W1,
                                    const float* __restrict__ W2) {
    int g = blockIdx.x;
    int layer = g >> 1;
    const float* src = ((g & 1) ? W2 : W1) + layer * FDIM * FDIM;
    for (int idx = threadIdx.x; idx < FDIM * FDIM; idx += blockDim.x) {
        int f = idx >> 7;
        int k = idx & 127;
        g_W[g][f * FDIM + (k ^ ((f & 7) << 3))] = __float2half_rn(src[idx]);
    }
}

// ---------------- main kernel: warp-specialized ----------------
__global__ __launch_bounds__(NTHR, 1)
void siren_ws_kernel(const float* __restrict__ coords,
                     const float* __restrict__ W_first,
                     const float* __restrict__ b_first,
                     const float* __restrict__ b1,
                     const float* __restrict__ b2,
                     const float* __restrict__ W_out,
                     const float* __restrict__ b_out,
                     float* __restrict__ out, int N) {
    extern __shared__ char smem[];
    const uint32_t sb = smem_u32(smem);
    float* cs = (float*)(smem + SMEM_CS);
    float* ybuf = (float*)(smem + SMEM_YBUF);

    const int tid  = threadIdx.x;
    const int w    = tid >> 5;
    const int lane = tid & 31;
    const bool is_mma = (w >= 4);          // wid 4-7: MMA (high arbiter priority)
    const int role = is_mma ? (w - 4) : w; // 0..3: feature block [32*role, +32)
    const int tg   = lane >> 2;
    const int t4   = lane & 3;
    const int li   = lane >> 3;
    const int lr   = lane & 7;
    const int P0   = blockIdx.x * TP;

    if (tid == 0) {
        MBAR_INIT(sb + SMEM_MB_W0, 1);
        MBAR_INIT(sb + SMEM_MB_W1, 1);
    }
    for (int t = tid; t < 3 * TP; t += NTHR) {
        int p = t / 3, dd = t - p * 3;
        int pg = min(P0 + p, N - 1);
        cs[t] = coords[pg * 3 + dd];
    }
    __syncthreads();

    if (tid == 0) {
        MBAR_EXPECT_TX(sb + SMEM_MB_W0, 32768u);
        BULK_G2S(sb + SMEM_WBUF0, (const void*)&g_W[0][0], 32768u, sb + SMEM_MB_W0);
        MBAR_EXPECT_TX(sb + SMEM_MB_W1, 32768u);
        BULK_G2S(sb + SMEM_WBUF1, (const void*)&g_W[1][0], 32768u, sb + SMEM_MB_W1);
    }

    // Epi thread state: pair j = (mi*8+nj)*2+cb owns feature f = 32*role+16*mi+tg+8*cb,
    // points n = half*64 + 8*nj + 2*t4 (+1). h2[half][j] = residual (2 points).
    float2 h2[2][32];

    // ---- first layer (epi warps only): h = sin(30*(Wx+b)) -> X_A, X_B ----
    if (!is_mma) {
        float wf0[2][2], wf1[2][2], wf2[2][2], bf[2][2];
#pragma unroll
        for (int mi = 0; mi < 2; mi++)
#pragma unroll
            for (int cb = 0; cb < 2; cb++) {
                const int f = 32 * role + 16 * mi + tg + 8 * cb;
                wf0[mi][cb] = __ldg(&W_first[f * 3]);
                wf1[mi][cb] = __ldg(&W_first[f * 3 + 1]);
                wf2[mi][cb] = __ldg(&W_first[f * 3 + 2]);
                bf[mi][cb]  = __ldg(&b_first[f]);
            }
#pragma unroll
        for (int half = 0; half < 2; half++) {
            char* xh = smem + (half ? SMEM_XB : SMEM_XA);
#pragma unroll
            for (int j = 0; j < 32; j++) {
                const int mi = j >> 4, nj = (j >> 1) & 7, cb = j & 1;
                const int nl = 8 * nj + 2 * t4;
                const int n = half * 64 + nl;
                float x0 = cs[n * 3], y0 = cs[n * 3 + 1], z0 = cs[n * 3 + 2];
                float x1 = cs[n * 3 + 3], y1 = cs[n * 3 + 4], z1 = cs[n * 3 + 5];
                float v0 = __sinf(OMEGA_W * fmaf(wf0[mi][cb], x0,
                              fmaf(wf1[mi][cb], y0, fmaf(wf2[mi][cb], z0, bf[mi][cb]))));
                float v1 = __sinf(OMEGA_W * fmaf(wf0[mi][cb], x1,
                              fmaf(wf1[mi][cb], y1, fmaf(wf2[mi][cb], z1, bf[mi][cb]))));
                h2[half][j] = make_float2(v0, v1);
                store_h16(xh, 32 * role + 16 * mi + tg + 8 * cb, nl, v0, v1);
            }
        }
    }
    __syncthreads();

    // ---- MMA half: 128x64x128, d staged to smem as float2 pairs ----
    auto mma_half = [&](uint32_t wbase, uint32_t xr, char* stg) {
        float d[2][8][4];
#pragma unroll
        for (int mi = 0; mi < 2; mi++)
#pragma unroll
            for (int nj = 0; nj < 8; nj++)
                d[mi][nj][0] = d[mi][nj][1] = d[mi][nj][2] = d[mi][nj][3] = 0.f;
        const int acol8 = (li >> 1) << 3;
        const int row8 = ((li & 1) << 3) + lr;
#pragma unroll
        for (int kk = 0; kk < 8; kk++) {
            const int k0 = kk << 4;
            uint32_t a[2][4], b[4][4];
#pragma unroll
            for (int mi = 0; mi < 2; mi++)
                LDSM_X4(a[mi], wbase + woff(32 * role + 16 * mi + row8, k0 + acol8));
            const int krow = k0 + row8;
#pragma unroll
            for (int q = 0; q < 4; q++)
                LDSM_X4T(b[q], xr + xo64(krow, q * 16 + acol8));
#pragma unroll
            for (int mi = 0; mi < 2; mi++)
#pragma unroll
                for (int q = 0; q < 4; q++) {
                    MMA16816(d[mi][2 * q],     a[mi], b[q][0], b[q][1]);
                    MMA16816(d[mi][2 * q + 1], a[mi], b[q][2], b[q][3]);
                }
        }
        // stage: pair j at float2 index role*1024 + j*32 + lane (conflict-free)
        float2* st = (float2*)stg;
#pragma unroll
        for (int mi = 0; mi < 2; mi++)
#pragma unroll
            for (int nj = 0; nj < 8; nj++) {
                const int jb = (mi * 8 + nj) * 2;
                st[role * 1024 + jb * 32 + lane] = make_float2(d[mi][nj][0], d[mi][nj][1]);
                st[role * 1024 + (jb + 1) * 32 + lane] = make_float2(d[mi][nj][2], d[mi][nj][3]);
            }
    };

    // ---- epilogue half for context ge ----
    auto epi_half = [&](int ge, int half) {
        const int layer = ge >> 1;
        const float2* st = (const float2*)(smem + (half ? SMEM_STGB : SMEM_STGA));
        char* xh = smem + (half ? SMEM_XB : SMEM_XA);
        if ((ge & 1) == 0) {
            const float w_in = (layer > 0) ? 0.5f : 1.0f;
            float bb[2][2];
#pragma unroll
            for (int mi = 0; mi < 2; mi++)
#pragma unroll
                for (int cb = 0; cb < 2; cb++)
                    bb[mi][cb] = __ldg(&b1[layer * FDIM + 32 * role + 16 * mi + tg + 8 * cb]);
#pragma unroll
            for (int j = 0; j < 32; j++) {
                const int mi = j >> 4, nj = (j >> 1) & 7, cb = j & 1;
                float2 dv = st[role * 1024 + j * 32 + lane];
                float s0 = __sinf(OMEGA_W * fmaf(w_in, dv.x, bb[mi][cb]));
                float s1 = __sinf(OMEGA_W * fmaf(w_in, dv.y, bb[mi][cb]));
                store_h16(xh, 32 * role + 16 * mi + tg + 8 * cb, 8 * nj + 2 * t4, s0, s1);
            }
        } else if (ge < NGEMM - 1) {
            float bb[2][2];
#pragma unroll
            for (int mi = 0; mi < 2; mi++)
#pragma unroll
                for (int cb = 0; cb < 2; cb++)
                    bb[mi][cb] = __ldg(&b2[layer * FDIM + 32 * role + 16 * mi + tg + 8 * cb]);
#pragma unroll
            for (int j = 0; j < 32; j++) {
                const int mi = j >> 4, nj = (j >> 1) & 7, cb = j & 1;
                float2 dv = st[role * 1024 + j * 32 + lane];
                float2 hv = h2[half][j];
                hv.x += __sinf(OMEGA_W * (dv.x + bb[mi][cb]));
                hv.y += __sinf(OMEGA_W * (dv.y + bb[mi][cb]));
                h2[half][j] = hv;
                store_h16(xh, 32 * role + 16 * mi + tg + 8 * cb, 8 * nj + 2 * t4, hv.x, hv.y);
            }
        } else {
            float bb[2][2], wo[2][2];
#pragma unroll
            for (int mi = 0; mi < 2; mi++)
#pragma unroll
                for (int cb = 0; cb < 2; cb++) {
                    const int f = 32 * role + 16 * mi + tg + 8 * cb;
                    bb[mi][cb] = __ldg(&b2[layer * FDIM + f]);
                    wo[mi][cb] = __ldg(&W_out[f]);
                }
            float p0s[8], p1s[8];
#pragma unroll
            for (int nj = 0; nj < 8; nj++) { p0s[nj] = 0.f; p1s[nj] = 0.f; }
#pragma unroll
            for (int mi = 0; mi < 2; mi++)
#pragma unroll
                for (int nj = 0; nj < 8; nj++) {
                    const int j0 = (mi * 8 + nj) * 2, j1 = j0 + 1;
                    float2 d0 = st[role * 1024 + j0 * 32 + lane];
                    float2 d1 = st[role * 1024 + j1 * 32 + lane];
                    float2 ha = h2[half][j0], hb = h2[half][j1];
                    float h0 = 0.5f * (ha.x + __sinf(OMEGA_W * (d0.x + bb[mi][0])));
                    float h1 = 0.5f * (ha.y + __sinf(OMEGA_W * (d0.y + bb[mi][0])));
                    float g2 = 0.5f * (hb.x + __sinf(OMEGA_W * (d1.x + bb[mi][1])));
                    float g3 = 0.5f * (hb.y + __sinf(OMEGA_W * (d1.y + bb[mi][1])));
                    p0s[nj] += fmaf(h0, wo[mi][0], g2 * wo[mi][1]);
                    p1s[nj] += fmaf(h1, wo[mi][0], g3 * wo[mi][1]);
                }
#pragma unroll
            for (int nj = 0; nj < 8; nj++) {
                float p0 = p0s[nj], p1 = p1s[nj];
#pragma unroll
                for (int m = 4; m <= 16; m <<= 1) {
                    p0 += __shfl_xor_sync(0xffffffffu, p0, m);
                    p1 += __shfl_xor_sync(0xffffffffu, p1, m);
                }
                if (tg == 0) {
                    const int n = half * 64 + 8 * nj + 2 * t4;
                    *reinterpret_cast<float2*>(&ybuf[role * TP + n]) = make_float2(p0, p1);
                }
            }
        }
    };

    // ---- pipelined slot loop ----
    for (int g = 0; g < NGEMM; g++) {
        const uint32_t wbase = sb + ((g & 1) ? SMEM_WBUF1 : SMEM_WBUF0);
        // slot 2g: MMA half A  ||  epi half B of g-1
        if (is_mma) {
            MBAR_WAIT(sb + ((g & 1) ? SMEM_MB_W1 : SMEM_MB_W0), (g >> 1) & 1);
            mma_half(wbase, sb + SMEM_XA, smem + SMEM_STGA);
        } else if (g > 0) {
            epi_half(g - 1, 1);
        }
        __syncthreads();
        // slot 2g+1: MMA half B  ||  epi half A of g
        if (is_mma) {
            mma_half(wbase, sb + SMEM_XB, smem + SMEM_STGB);
        } else {
            epi_half(g, 0);
        }
        __syncthreads();
        if (tid == 0 && g + 2 < NGEMM) {
            uint32_t mb = sb + ((g & 1) ? SMEM_MB_W1 : SMEM_MB_W0);
            uint32_t wbuf = sb + ((g & 1) ? SMEM_WBUF1 : SMEM_WBUF0);
            MBAR_EXPECT_TX(mb, 32768u);
            BULK_G2S(wbuf, (const void*)&g_W[g + 2][0], 32768u, mb);
        }
    }

    // ---- tail: epi half B of last GEMM (final type) ----
    if (!is_mma) epi_half(NGEMM - 1, 1);
    __syncthreads();

    // ---- cross-warp output reduction ----
    if (tid < TP) {
        int p = tid;
        if (P0 + p < N) {
            float y = __ldg(&b_out[0]) + ybuf[p] + ybuf[TP + p]
                    + ybuf[2 * TP + p] + ybuf[3 * TP + p];
            out[P0 + p] = y;
        }
    }
}

extern "C" void kernel_launch(void* const* d_in, const int* in_sizes, int n_in,
                              void* d_out, int out_size) {
    const float* coords  = (const float*)d_in[0];
    const float* W_first = (const float*)d_in[1];
    const float* b_first = (const float*)d_in[2];
    const float* W1      = (const float*)d_in[3];
    const float* b1      = (const float*)d_in[4];
    const float* W2      = (const float*)d_in[5];
    const float* b2      = (const float*)d_in[6];
    const float* W_out   = (const float*)d_in[7];
    const float* b_out   = (const float*)d_in[8];
    const int N = in_sizes[0] / 3;

    prep_weights_kernel<<<NGEMM, 256>>>(W1, W2);

    cudaFuncSetAttribute(siren_ws_kernel,
                         cudaFuncAttributeMaxDynamicSharedMemorySize, SMEM_TOTAL);

    const int nblocks = (N + TP - 1) / TP;
    siren_ws_kernel<<<nblocks, NTHR, SMEM_TOTAL>>>(coords, W_first, b_first,
                                                   b1, b2, W_out, b_out,
                                                   (float*)d_out, N);
}